// round 12
// baseline (speedup 1.0000x reference)
#include <cuda_runtime.h>
#include <cuda_fp16.h>
#include <cstdint>
#include <math.h>

#define BB   2048
#define NN   65536
#define PDIM 512
#define TDIM 256
#define CDIM 768
#define HDIM 64
#define RDIM 128
#define KK   16
#define MM   64   // screening candidates per row

// ---------------- scratch (device globals; no allocations) ----------------
__device__ float g_bcatT[CDIM * NN];            // bank concat, d-major
__device__ float g_qcatT[CDIM * BB];            // query concat, d-major
__device__ float g_WqT[CDIM * RDIM];
__device__ float g_WkT[CDIM * RDIM];
__device__ float g_qrow[BB * RDIM];             // normalized q, row-major fp32
__device__ float g_krow[(size_t)NN * RDIM];     // normalized k, row-major fp32
__device__ unsigned int g_q16[(RDIM / 2) * BB]; // q fp16, d-major half2 planes
__device__ unsigned int g_k16[(size_t)(RDIM / 2) * NN];
__device__ __half g_sim16[(size_t)BB * NN];     // screened sims (fp16, masked=-65504)
__device__ int   g_topidx[BB * KK];
__device__ float g_r[BB * RDIM];
__device__ int   g_hasvalid[BB];

// output layout (floats)
#define OUT_TS (BB * PDIM)
#define OUT_TI (OUT_TS + BB * KK)
#define OUT_AL (OUT_TI + BB * KK)

// =====================================================================
// Prep A: transpose Wq/Wk [128][768] -> WT [768][128]
// =====================================================================
__global__ void wT_kernel(const float* __restrict__ Wq, const float* __restrict__ Wk)
{
    __shared__ float t[32][33];
    const float* src = blockIdx.z ? Wk : Wq;
    float* dst = blockIdx.z ? g_WkT : g_WqT;
    int c0 = blockIdx.x * 32;
    int r0 = blockIdx.y * 32;
#pragma unroll
    for (int i = 0; i < 4; i++)
        t[threadIdx.y + i * 8][threadIdx.x] = src[(size_t)(r0 + threadIdx.y + i * 8) * CDIM + c0 + threadIdx.x];
    __syncthreads();
#pragma unroll
    for (int i = 0; i < 4; i++)
        dst[(size_t)(c0 + threadIdx.y + i * 8) * RDIM + r0 + threadIdx.x] = t[threadIdx.x][threadIdx.y + i * 8];
}

// =====================================================================
// Prep B: concat+transpose  (rows x [z|g])  ->  catT [768][NR]
// =====================================================================
__global__ void catT_kernel(const float* __restrict__ z, const float* __restrict__ g,
                            float* __restrict__ catT, int NR)
{
    __shared__ float t[32][33];
    int n0 = blockIdx.x * 32;
    int d0 = blockIdx.y * 32;
#pragma unroll
    for (int i = 0; i < 4; i++) {
        int n = n0 + threadIdx.y + i * 8;
        int d = d0 + threadIdx.x;
        float v = (d0 < PDIM) ? z[(size_t)n * PDIM + d]
                              : g[(size_t)n * TDIM + (d - PDIM)];
        t[threadIdx.y + i * 8][threadIdx.x] = v;
    }
    __syncthreads();
#pragma unroll
    for (int i = 0; i < 4; i++)
        catT[(size_t)(d0 + threadIdx.y + i * 8) * NR + n0 + threadIdx.x] = t[threadIdx.x][threadIdx.y + i * 8];
}

// =====================================================================
// Proj GEMM + L2 norm (scalar fp32).  Emits:
//   rowout: fp32 row-major [NR][128]
//   h2out:  fp16 d-major half2 planes [(128/2)][NR] (as uint)
// =====================================================================
__global__ void __launch_bounds__(256, 1) proj_gemm_kernel(
    const float* __restrict__ catT, const float* __restrict__ WT,
    const float* __restrict__ bias, float* __restrict__ rowout,
    unsigned int* __restrict__ h2out, int NR)
{
    extern __shared__ float dyn[];
    float* is = dyn;            // [32][128]
    float* ws = dyn + 4096;     // [32][128]
    __shared__ float invs[128];

    const int tid = threadIdx.x;
    const int tx = tid & 15;
    const int ty = tid >> 4;
    const int row0 = blockIdx.x * 128;

    float acc[8][8];
#pragma unroll
    for (int m = 0; m < 8; m++) {
        float bv = bias[tx * 8 + m];
#pragma unroll
        for (int j = 0; j < 8; j++) acc[j][m] = bv;
    }

    for (int kt = 0; kt < 24; kt++) {
#pragma unroll
        for (int it = 0; it < 4; it++) {
            int idx = tid + it * 256;
            int dd = idx >> 5, c4 = idx & 31;
            *(float4*)&is[dd * 128 + c4 * 4] =
                *(const float4*)&catT[(size_t)(kt * 32 + dd) * NR + row0 + c4 * 4];
            *(float4*)&ws[dd * 128 + c4 * 4] =
                *(const float4*)&WT[(size_t)(kt * 32 + dd) * RDIM + c4 * 4];
        }
        __syncthreads();
#pragma unroll 4
        for (int dd = 0; dd < 32; dd++) {
            float a[8], b[8];
            *(float4*)&a[0] = *(float4*)&is[dd * 128 + ty * 8];
            *(float4*)&a[4] = *(float4*)&is[dd * 128 + ty * 8 + 4];
            *(float4*)&b[0] = *(float4*)&ws[dd * 128 + tx * 8];
            *(float4*)&b[4] = *(float4*)&ws[dd * 128 + tx * 8 + 4];
#pragma unroll
            for (int j = 0; j < 8; j++)
#pragma unroll
                for (int m = 0; m < 8; m++)
                    acc[j][m] += a[j] * b[m];
        }
        __syncthreads();
    }

    // row sum-of-squares reduction across the 16 tx groups
    float* red = dyn;   // [128][16]
#pragma unroll
    for (int j = 0; j < 8; j++) {
        float p = 0.f;
#pragma unroll
        for (int m = 0; m < 8; m++) p += acc[j][m] * acc[j][m];
        red[(ty * 8 + j) * 16 + tx] = p;
    }
    __syncthreads();
    if (tid < 128) {
        float ss = 0.f;
#pragma unroll
        for (int t = 0; t < 16; t++) ss += red[tid * 16 + t];
        invs[tid] = 1.0f / fmaxf(sqrtf(ss), 1e-12f);
    }
    __syncthreads();

    // fp32 row-major emit (direct from regs)
#pragma unroll
    for (int j = 0; j < 8; j++) {
        float iv = invs[ty * 8 + j];
        float v[8];
#pragma unroll
        for (int m = 0; m < 8; m++) v[m] = acc[j][m] * iv;
        float* dst = rowout + (size_t)(row0 + ty * 8 + j) * RDIM + tx * 8;
        *(float4*)dst = make_float4(v[0], v[1], v[2], v[3]);
        *(float4*)(dst + 4) = make_float4(v[4], v[5], v[6], v[7]);
    }

    // stage normalized values [col][row] then fp16 d-major half2 emit
    float* os = dyn;    // [128 col][129]
#pragma unroll
    for (int j = 0; j < 8; j++) {
        float iv = invs[ty * 8 + j];
#pragma unroll
        for (int m = 0; m < 8; m++)
            os[(tx * 8 + m) * 129 + ty * 8 + j] = acc[j][m] * iv;
    }
    __syncthreads();
    for (int it = 0; it < 32; it++) {
        int idx = tid + it * 256;          // 0..8191 over (c 0..63, r 0..127)
        int c = idx >> 7, r = idx & 127;
        __half h0 = __float2half_rn(os[(2 * c) * 129 + r]);
        __half h1 = __float2half_rn(os[(2 * c + 1) * 129 + r]);
        unsigned int u = (unsigned int)__half_as_ushort(h0) |
                         ((unsigned int)__half_as_ushort(h1) << 16);
        h2out[(size_t)c * NR + row0 + r] = u;
    }
}

// =====================================================================
// Screening GEMM: sim16 = fp16(q @ k^T), masked -> -65504 sentinel.
// HFMA2 over packed d-pairs.  Block 128q x 128k, 8x8 microtile.
// =====================================================================
__global__ void __launch_bounds__(256, 2) screen_kernel(const unsigned int* __restrict__ mask)
{
    extern __shared__ unsigned int su[];
    unsigned int* qs2 = su;            // [64 d2][128 q]
    unsigned int* ks2 = su + 64 * 128; // [64 d2][128 k]

    const int tid = threadIdx.x;
    const int tx = tid & 15;
    const int ty = tid >> 4;
    const int kc0 = blockIdx.x * 128;
    const int qr0 = blockIdx.y * 128;

#pragma unroll
    for (int it = 0; it < 8; it++) {
        int idx = tid + it * 256;          // 2048 uint4 slots per tile
        int d2 = idx >> 5, c4 = idx & 31;
        *(uint4*)&qs2[d2 * 128 + c4 * 4] =
            *(const uint4*)&g_q16[(size_t)d2 * BB + qr0 + c4 * 4];
        *(uint4*)&ks2[d2 * 128 + c4 * 4] =
            *(const uint4*)&g_k16[(size_t)d2 * NN + kc0 + c4 * 4];
    }
    __syncthreads();

    __half2 acc[8][8];
    const __half2 z2 = __float2half2_rn(0.f);
#pragma unroll
    for (int j = 0; j < 8; j++)
#pragma unroll
        for (int m = 0; m < 8; m++) acc[j][m] = z2;

#pragma unroll 4
    for (int d2 = 0; d2 < 64; d2++) {
        unsigned int a[8], b[8];
        *(uint4*)&a[0] = *(uint4*)&qs2[d2 * 128 + ty * 8];
        *(uint4*)&a[4] = *(uint4*)&qs2[d2 * 128 + ty * 8 + 4];
        *(uint4*)&b[0] = *(uint4*)&ks2[d2 * 128 + tx * 8];
        *(uint4*)&b[4] = *(uint4*)&ks2[d2 * 128 + tx * 8 + 4];
#pragma unroll
        for (int j = 0; j < 8; j++) {
            __half2 av = *reinterpret_cast<__half2*>(&a[j]);
#pragma unroll
            for (int m = 0; m < 8; m++) {
                __half2 bv = *reinterpret_cast<__half2*>(&b[m]);
                acc[j][m] = __hfma2(av, bv, acc[j][m]);
            }
        }
    }

    const __half SENT = __ushort_as_half((unsigned short)0xFBFF);  // -65504
#pragma unroll
    for (int j = 0; j < 8; j++) {
        int row = qr0 + ty * 8 + j;
        const unsigned int* mrow = mask + (size_t)row * NN + kc0 + tx * 8;
        uint4 mA = *(const uint4*)mrow;
        uint4 mB = *(const uint4*)(mrow + 4);
        unsigned int mv[8] = {mA.x, mA.y, mA.z, mA.w, mB.x, mB.y, mB.z, mB.w};
        __half h[8];
#pragma unroll
        for (int m = 0; m < 8; m++) {
            float f = __low2float(acc[j][m]) + __high2float(acc[j][m]);
            h[m] = mv[m] ? __float2half_rn(f) : SENT;
        }
        unsigned int pk[4];
#pragma unroll
        for (int p = 0; p < 4; p++)
            pk[p] = (unsigned int)__half_as_ushort(h[2 * p]) |
                    ((unsigned int)__half_as_ushort(h[2 * p + 1]) << 16);
        *(uint4*)&g_sim16[(size_t)row * NN + kc0 + tx * 8] =
            make_uint4(pk[0], pk[1], pk[2], pk[3]);
    }
}

// =====================================================================
// Select top-64 candidates from fp16 screen, rescore in fp32 with the
// SAME sequential-FMA accumulation as the passing full-sim kernels
// (error correlated with the reference's fp32 -> same near-tie ordering),
// emit top-16.
// =====================================================================
__device__ __forceinline__ void topk_push(float v, int n, float* lv, int* li)
{
    if (v > lv[15] || (v == lv[15] && n < li[15])) {
        float cv = v; int ci = n;
#pragma unroll
        for (int j = 0; j < 16; j++) {
            bool better = (cv > lv[j]) || (cv == lv[j] && ci < li[j]);
            float tv = lv[j]; int ti = li[j];
            if (better) { lv[j] = cv; li[j] = ci; cv = tv; ci = ti; }
        }
    }
}

__global__ void __launch_bounds__(256) select_rescore_kernel(float* __restrict__ out)
{
    __shared__ float sv[4096];
    __shared__ int   si[4096];
    __shared__ float rv[256];
    __shared__ int   ri[256];
    __shared__ int   rp[256];
    __shared__ int   anyv[256];
    __shared__ float cval[MM];
    __shared__ int   cidx[MM];
    __shared__ float rsc[MM];
    __shared__ float qsh[128];

    const int b = blockIdx.x, tid = threadIdx.x;
    const uint4* s4 = (const uint4*)(g_sim16 + (size_t)b * NN);  // 8 halves each

    if (tid < 128) qsh[tid] = g_qrow[(size_t)b * RDIM + tid];

    float lv[16]; int li[16];
#pragma unroll
    for (int j = 0; j < 16; j++) { lv[j] = -INFINITY; li[j] = 0x7fffffff; }
    int hv = 0;

    for (int it = 0; it < 32; it++) {
        int u = tid + it * 256;            // uint4 index, 8192 per row
        uint4 w = s4[u];
        unsigned int ws[4] = {w.x, w.y, w.z, w.w};
        int n0 = u * 8;
#pragma unroll
        for (int p = 0; p < 4; p++) {
            __half2 h2 = *reinterpret_cast<__half2*>(&ws[p]);
            float lo = __low2float(h2), hi = __high2float(h2);
            hv |= (lo > -60000.f) | (hi > -60000.f);
            topk_push(lo, n0 + 2 * p, lv, li);
            topk_push(hi, n0 + 2 * p + 1, lv, li);
        }
    }
#pragma unroll
    for (int j = 0; j < 16; j++) { sv[tid * 16 + j] = lv[j]; si[tid * 16 + j] = li[j]; }
    anyv[tid] = hv;
    __syncthreads();
    for (int s = 128; s > 0; s >>= 1) {
        if (tid < s) anyv[tid] |= anyv[tid + s];
        __syncthreads();
    }
    if (tid == 0) g_hasvalid[b] = anyv[0];

    // extract top-MM candidates (value desc, idx asc tie-break)
    int p = 0;
    for (int r = 0; r < MM; r++) {
        float v = (p < 16) ? sv[tid * 16 + p] : -INFINITY;
        int   i = (p < 16) ? si[tid * 16 + p] : 0x7fffffff;
        rv[tid] = v; ri[tid] = i; rp[tid] = tid;
        __syncthreads();
        for (int s = 128; s > 0; s >>= 1) {
            if (tid < s) {
                float v2 = rv[tid + s]; int i2 = ri[tid + s];
                if (v2 > rv[tid] || (v2 == rv[tid] && i2 < ri[tid])) {
                    rv[tid] = v2; ri[tid] = i2; rp[tid] = rp[tid + s];
                }
            }
            __syncthreads();
        }
        if (tid == 0) { cval[r] = rv[0]; cidx[r] = ri[0]; }
        int owner = rp[0];
        __syncthreads();
        if (tid == owner) p++;
        __syncthreads();
    }

    // rescore candidates: one thread per candidate, fp32 sequential
    // accumulation replicating the Round-3/5/8 passing sim kernels:
    //   acc += qx*kx + qy*ky + qz*kz + qw*kw   over d4 = 0..31 in order
    if (tid < MM) {
        int idx = cidx[tid];
        const float4* kr = (const float4*)(g_krow + (size_t)idx * RDIM);
        float acc = 0.f;
        for (int d4 = 0; d4 < 32; d4++) {
            float4 kv = kr[d4];
            float4 qv = *(const float4*)&qsh[d4 * 4];
            acc += qv.x * kv.x + qv.y * kv.y + qv.z * kv.z + qv.w * kv.w;
        }
        rsc[tid] = (cval[tid] < -60000.f) ? -1e9f : acc;
    }
    __syncthreads();

    // final top-16 (serial, thread 0) on fp32 rescored values
    if (tid == 0) {
        bool used[MM];
#pragma unroll
        for (int c = 0; c < MM; c++) used[c] = false;
        for (int r = 0; r < 16; r++) {
            float bvv = -INFINITY; int bii = 0x7fffffff, bc = -1;
            for (int c = 0; c < MM; c++) {
                if (used[c]) continue;
                if (rsc[c] > bvv || (rsc[c] == bvv && cidx[c] < bii)) {
                    bvv = rsc[c]; bii = cidx[c]; bc = c;
                }
            }
            used[bc] = true;
            out[OUT_TS + b * 16 + r] = bvv;
            out[OUT_TI + b * 16 + r] = (float)bii;
            g_topidx[b * 16 + r] = bii;
        }
    }
}

// =====================================================================
// per-row attention stack
// =====================================================================
__global__ void __launch_bounds__(128) attn_kernel(
    const float* __restrict__ bank_y,
    const float* __restrict__ Ws1, const float* __restrict__ bs1,
    const float* __restrict__ Ws2, const float* __restrict__ bs2,
    const float* __restrict__ Wc1, const float* __restrict__ bc1,
    const float* __restrict__ Wc2, const float* __restrict__ bc2,
    float* __restrict__ out)
{
    __shared__ float y[16][64];
    __shared__ float hbuf[16][128];
    __shared__ float proj[16][128];
    __shared__ float qv[128];
    __shared__ float cmat[128 * 16];
    __shared__ float tred[8 * 16];
    __shared__ float lg[16];
    __shared__ float alpha[16];
    __shared__ int   tix[16];

    const int b = blockIdx.x, tid = threadIdx.x;
    if (tid < 16) tix[tid] = g_topidx[b * 16 + tid];
    qv[tid] = g_qrow[(size_t)b * RDIM + tid];
    __syncthreads();

    for (int e = tid; e < 16 * 64; e += 128)
        y[e >> 6][e & 63] = bank_y[(size_t)tix[e >> 6] * 64 + (e & 63)];
    __syncthreads();

    const int r = tid;
    {
        float4 w[16];
        const float4* W4 = (const float4*)(Ws1 + (size_t)r * 64);
#pragma unroll
        for (int i = 0; i < 16; i++) w[i] = W4[i];
        float bv = bs1[r];
        for (int j = 0; j < 16; j++) {
            float s = bv;
#pragma unroll
            for (int i = 0; i < 16; i++) {
                float4 yy = *(const float4*)&y[j][i * 4];
                s += w[i].x * yy.x + w[i].y * yy.y + w[i].z * yy.z + w[i].w * yy.w;
            }
            hbuf[j][r] = fmaxf(s, 0.f);
        }
    }
    __syncthreads();
    {
        float accp[16];
        float bv = bs2[r];
#pragma unroll
        for (int j = 0; j < 16; j++) accp[j] = bv;
        const float4* W4 = (const float4*)(Ws2 + (size_t)r * 128);
        for (int i = 0; i < 32; i++) {
            float4 w = W4[i];
#pragma unroll
            for (int j = 0; j < 16; j++) {
                float4 hh = *(const float4*)&hbuf[j][i * 4];
                accp[j] += w.x * hh.x + w.y * hh.y + w.z * hh.z + w.w * hh.w;
            }
        }
#pragma unroll
        for (int j = 0; j < 16; j++) proj[j][r] = accp[j];
    }
    __syncthreads();

    {
        float uqr = bc1[r];
        const float4* Wq4 = (const float4*)(Wc1 + (size_t)r * 256);
        for (int i = 0; i < 32; i++) {
            float4 w = Wq4[i];
            float4 qq = *(const float4*)&qv[i * 4];
            uqr += w.x * qq.x + w.y * qq.y + w.z * qq.z + w.w * qq.w;
        }
        float sacc[16];
#pragma unroll
        for (int j = 0; j < 16; j++) sacc[j] = uqr;
        const float4* Wp4 = (const float4*)(Wc1 + (size_t)r * 256 + 128);
        for (int i = 0; i < 32; i++) {
            float4 w = Wp4[i];
#pragma unroll
            for (int j = 0; j < 16; j++) {
                float4 pp = *(const float4*)&proj[j][i * 4];
                sacc[j] += w.x * pp.x + w.y * pp.y + w.z * pp.z + w.w * pp.w;
            }
        }
        float w2r = Wc2[r];
#pragma unroll
        for (int j = 0; j < 16; j++) cmat[r * 16 + j] = tanhf(sacc[j]) * w2r;
    }
    __syncthreads();
    {
        int j = tid & 15, c = tid >> 4;
        float s = 0.f;
        for (int i = 0; i < 16; i++) s += cmat[(c * 16 + i) * 16 + j];
        tred[c * 16 + j] = s;
    }
    __syncthreads();
    if (tid < 16) {
        float s = bc2[0];
        for (int c = 0; c < 8; c++) s += tred[c * 16 + tid];
        lg[tid] = s;
    }
    __syncthreads();
    if (tid == 0) {
        if (g_hasvalid[b]) {
            float mx = lg[0];
            for (int j = 1; j < 16; j++) mx = fmaxf(mx, lg[j]);
            float se = 0.f, ev[16];
            for (int j = 0; j < 16; j++) { ev[j] = expf(lg[j] - mx); se += ev[j]; }
            float isv = 1.0f / se;
            for (int j = 0; j < 16; j++) alpha[j] = ev[j] * isv;
        } else {
            for (int j = 0; j < 16; j++) alpha[j] = 0.f;
        }
    }
    __syncthreads();
    if (tid < 16) out[OUT_AL + b * 16 + tid] = alpha[tid];
    {
        float s = 0.f;
#pragma unroll
        for (int j = 0; j < 16; j++) s += alpha[j] * proj[j][tid];
        g_r[(size_t)b * 128 + tid] = s;
    }
}

// =====================================================================
// z_tilde = has_valid ? relu([z,r] @ Wa^T + ba) : z
// =====================================================================
__global__ void __launch_bounds__(256) aug_kernel(
    const float* __restrict__ zin, const float* __restrict__ Wa,
    const float* __restrict__ ba, float* __restrict__ out)
{
    __shared__ float zr[16 * 640];
    __shared__ int   hv[16];
    const int tid = threadIdx.x, b0 = blockIdx.x * 16;

    for (int e = tid; e < 16 * PDIM; e += 256) {
        int j = e / PDIM, d = e - j * PDIM;
        zr[j * 640 + d] = zin[(size_t)(b0 + j) * PDIM + d];
    }
    for (int e = tid; e < 16 * RDIM; e += 256) {
        int j = e >> 7, d = e & 127;
        zr[j * 640 + PDIM + d] = g_r[(size_t)(b0 + j) * RDIM + d];
    }
    if (tid < 16) hv[tid] = g_hasvalid[b0 + tid];
    __syncthreads();

    for (int half = 0; half < 2; half++) {
        int o = tid + half * 256;
        float acc[16];
        float bv = ba[o];
#pragma unroll
        for (int j = 0; j < 16; j++) acc[j] = bv;
        const float4* W4 = (const float4*)(Wa + (size_t)o * 640);
        for (int i = 0; i < 160; i++) {
            float4 w = W4[i];
#pragma unroll
            for (int j = 0; j < 16; j++) {
                float4 zz = *(const float4*)&zr[j * 640 + i * 4];
                acc[j] += w.x * zz.x + w.y * zz.y + w.z * zz.z + w.w * zz.w;
            }
        }
#pragma unroll
        for (int j = 0; j < 16; j++) {
            float v = hv[j] ? fmaxf(acc[j], 0.f) : zr[j * 640 + o];
            out[(size_t)(b0 + j) * PDIM + o] = v;
        }
    }
}

// =====================================================================
extern "C" void kernel_launch(void* const* d_in, const int* in_sizes, int n_in,
                              void* d_out, int out_size)
{
    const float* z_i    = (const float*)d_in[0];
    const float* g_i    = (const float*)d_in[1];
    const float* bank_z = (const float*)d_in[2];
    const float* bank_g = (const float*)d_in[3];
    const float* bank_y = (const float*)d_in[4];
    const unsigned int* vmask = (const unsigned int*)d_in[5];
    const float* Wq  = (const float*)d_in[6];
    const float* bq  = (const float*)d_in[7];
    const float* Wk  = (const float*)d_in[8];
    const float* bk  = (const float*)d_in[9];
    const float* Ws1 = (const float*)d_in[10];
    const float* bs1 = (const float*)d_in[11];
    const float* Ws2 = (const float*)d_in[12];
    const float* bs2 = (const float*)d_in[13];
    const float* Wc1 = (const float*)d_in[14];
    const float* bc1 = (const float*)d_in[15];
    const float* Wc2 = (const float*)d_in[16];
    const float* bc2 = (const float*)d_in[17];
    const float* Wa  = (const float*)d_in[18];
    const float* ba  = (const float*)d_in[19];
    float* out = (float*)d_out;

    float* p_bcatT; cudaGetSymbolAddress((void**)&p_bcatT, g_bcatT);
    float* p_qcatT; cudaGetSymbolAddress((void**)&p_qcatT, g_qcatT);
    float* p_WqT;   cudaGetSymbolAddress((void**)&p_WqT, g_WqT);
    float* p_WkT;   cudaGetSymbolAddress((void**)&p_WkT, g_WkT);
    float* p_qrow;  cudaGetSymbolAddress((void**)&p_qrow, g_qrow);
    float* p_krow;  cudaGetSymbolAddress((void**)&p_krow, g_krow);
    unsigned int* p_q16; cudaGetSymbolAddress((void**)&p_q16, g_q16);
    unsigned int* p_k16; cudaGetSymbolAddress((void**)&p_k16, g_k16);

    const int smemProj   = 16512 * 4;  // 66 KB
    const int smemScreen = 65536;      // 64 KB

    cudaFuncSetAttribute(proj_gemm_kernel, cudaFuncAttributeMaxDynamicSharedMemorySize, smemProj);
    cudaFuncSetAttribute(screen_kernel, cudaFuncAttributeMaxDynamicSharedMemorySize, smemScreen);

    wT_kernel<<<dim3(24, 4, 2), dim3(32, 8)>>>(Wq, Wk);
    catT_kernel<<<dim3(NN / 32, 24), dim3(32, 8)>>>(bank_z, bank_g, p_bcatT, NN);
    catT_kernel<<<dim3(BB / 32, 24), dim3(32, 8)>>>(z_i, g_i, p_qcatT, BB);

    proj_gemm_kernel<<<BB / 128, 256, smemProj>>>(p_qcatT, p_WqT, bq, p_qrow, p_q16, BB);
    proj_gemm_kernel<<<NN / 128, 256, smemProj>>>(p_bcatT, p_WkT, bk, p_krow, p_k16, NN);

    screen_kernel<<<dim3(NN / 128, BB / 128), 256, smemScreen>>>(vmask);
    select_rescore_kernel<<<BB, 256>>>(out);
    attn_kernel<<<BB, 128>>>(bank_y, Ws1, bs1, Ws2, bs2, Wc1, bc1, Wc2, bc2, out);
    aug_kernel<<<BB / 16, 256>>>(z_i, Wa, ba, out);
}

// round 14
// speedup vs baseline: 1.1688x; 1.1688x over previous
#include <cuda_runtime.h>
#include <cuda_fp16.h>
#include <cstdint>
#include <math.h>

#define BB   2048
#define NN   65536
#define PDIM 512
#define TDIM 256
#define CDIM 768
#define HDIM 64
#define RDIM 128
#define KK   16
#define MM   64       // rescore candidates per row (validated in Round 12)
#define NTILE 512     // k-tiles of 128 per row

// ---------------- scratch (device globals; no allocations) ----------------
__device__ float g_bcatT[CDIM * NN];            // bank concat, d-major
__device__ float g_qcatT[CDIM * BB];            // query concat, d-major
__device__ float g_WqT[CDIM * RDIM];
__device__ float g_WkT[CDIM * RDIM];
__device__ float g_qrow[BB * RDIM];             // normalized q, row-major fp32
__device__ float g_krow[(size_t)NN * RDIM];     // normalized k, row-major fp32
__device__ unsigned int g_q16[(RDIM / 2) * BB]; // q fp16, d-major half2 planes
__device__ unsigned int g_k16[(size_t)(RDIM / 2) * NN];
__device__ __half g_sim16[(size_t)BB * NN];     // screened sims (fp16, masked=-65504)
__device__ float g_tmax[(size_t)BB * NTILE];    // per-(row, ktile) max of stored fp16
__device__ int   g_topidx[BB * KK];
__device__ float g_r[BB * RDIM];
__device__ int   g_hasvalid[BB];

// output layout (floats)
#define OUT_TS (BB * PDIM)
#define OUT_TI (OUT_TS + BB * KK)
#define OUT_AL (OUT_TI + BB * KK)

// =====================================================================
// Prep A: transpose Wq/Wk [128][768] -> WT [768][128]
// =====================================================================
__global__ void wT_kernel(const float* __restrict__ Wq, const float* __restrict__ Wk)
{
    __shared__ float t[32][33];
    const float* src = blockIdx.z ? Wk : Wq;
    float* dst = blockIdx.z ? g_WkT : g_WqT;
    int c0 = blockIdx.x * 32;
    int r0 = blockIdx.y * 32;
#pragma unroll
    for (int i = 0; i < 4; i++)
        t[threadIdx.y + i * 8][threadIdx.x] = src[(size_t)(r0 + threadIdx.y + i * 8) * CDIM + c0 + threadIdx.x];
    __syncthreads();
#pragma unroll
    for (int i = 0; i < 4; i++)
        dst[(size_t)(c0 + threadIdx.y + i * 8) * RDIM + r0 + threadIdx.x] = t[threadIdx.x][threadIdx.y + i * 8];
}

// =====================================================================
// Prep B: concat+transpose  (rows x [z|g])  ->  catT [768][NR]
// =====================================================================
__global__ void catT_kernel(const float* __restrict__ z, const float* __restrict__ g,
                            float* __restrict__ catT, int NR)
{
    __shared__ float t[32][33];
    int n0 = blockIdx.x * 32;
    int d0 = blockIdx.y * 32;
#pragma unroll
    for (int i = 0; i < 4; i++) {
        int n = n0 + threadIdx.y + i * 8;
        int d = d0 + threadIdx.x;
        float v = (d0 < PDIM) ? z[(size_t)n * PDIM + d]
                              : g[(size_t)n * TDIM + (d - PDIM)];
        t[threadIdx.y + i * 8][threadIdx.x] = v;
    }
    __syncthreads();
#pragma unroll
    for (int i = 0; i < 4; i++)
        catT[(size_t)(d0 + threadIdx.y + i * 8) * NR + n0 + threadIdx.x] = t[threadIdx.x][threadIdx.y + i * 8];
}

// =====================================================================
// Proj GEMM + L2 norm (scalar fp32).  Emits fp32 row-major + fp16 d-major.
// =====================================================================
__global__ void __launch_bounds__(256, 1) proj_gemm_kernel(
    const float* __restrict__ catT, const float* __restrict__ WT,
    const float* __restrict__ bias, float* __restrict__ rowout,
    unsigned int* __restrict__ h2out, int NR)
{
    extern __shared__ float dyn[];
    float* is = dyn;            // [32][128]
    float* ws = dyn + 4096;     // [32][128]
    __shared__ float invs[128];

    const int tid = threadIdx.x;
    const int tx = tid & 15;
    const int ty = tid >> 4;
    const int row0 = blockIdx.x * 128;

    float acc[8][8];
#pragma unroll
    for (int m = 0; m < 8; m++) {
        float bv = bias[tx * 8 + m];
#pragma unroll
        for (int j = 0; j < 8; j++) acc[j][m] = bv;
    }

    for (int kt = 0; kt < 24; kt++) {
#pragma unroll
        for (int it = 0; it < 4; it++) {
            int idx = tid + it * 256;
            int dd = idx >> 5, c4 = idx & 31;
            *(float4*)&is[dd * 128 + c4 * 4] =
                *(const float4*)&catT[(size_t)(kt * 32 + dd) * NR + row0 + c4 * 4];
            *(float4*)&ws[dd * 128 + c4 * 4] =
                *(const float4*)&WT[(size_t)(kt * 32 + dd) * RDIM + c4 * 4];
        }
        __syncthreads();
#pragma unroll 4
        for (int dd = 0; dd < 32; dd++) {
            float a[8], b[8];
            *(float4*)&a[0] = *(float4*)&is[dd * 128 + ty * 8];
            *(float4*)&a[4] = *(float4*)&is[dd * 128 + ty * 8 + 4];
            *(float4*)&b[0] = *(float4*)&ws[dd * 128 + tx * 8];
            *(float4*)&b[4] = *(float4*)&ws[dd * 128 + tx * 8 + 4];
#pragma unroll
            for (int j = 0; j < 8; j++)
#pragma unroll
                for (int m = 0; m < 8; m++)
                    acc[j][m] += a[j] * b[m];
        }
        __syncthreads();
    }

    float* red = dyn;   // [128][16]
#pragma unroll
    for (int j = 0; j < 8; j++) {
        float p = 0.f;
#pragma unroll
        for (int m = 0; m < 8; m++) p += acc[j][m] * acc[j][m];
        red[(ty * 8 + j) * 16 + tx] = p;
    }
    __syncthreads();
    if (tid < 128) {
        float ss = 0.f;
#pragma unroll
        for (int t = 0; t < 16; t++) ss += red[tid * 16 + t];
        invs[tid] = 1.0f / fmaxf(sqrtf(ss), 1e-12f);
    }
    __syncthreads();

#pragma unroll
    for (int j = 0; j < 8; j++) {
        float iv = invs[ty * 8 + j];
        float v[8];
#pragma unroll
        for (int m = 0; m < 8; m++) v[m] = acc[j][m] * iv;
        float* dst = rowout + (size_t)(row0 + ty * 8 + j) * RDIM + tx * 8;
        *(float4*)dst = make_float4(v[0], v[1], v[2], v[3]);
        *(float4*)(dst + 4) = make_float4(v[4], v[5], v[6], v[7]);
    }

    float* os = dyn;    // [128 col][129]
#pragma unroll
    for (int j = 0; j < 8; j++) {
        float iv = invs[ty * 8 + j];
#pragma unroll
        for (int m = 0; m < 8; m++)
            os[(tx * 8 + m) * 129 + ty * 8 + j] = acc[j][m] * iv;
    }
    __syncthreads();
    for (int it = 0; it < 32; it++) {
        int idx = tid + it * 256;
        int c = idx >> 7, r = idx & 127;
        __half h0 = __float2half_rn(os[(2 * c) * 129 + r]);
        __half h1 = __float2half_rn(os[(2 * c + 1) * 129 + r]);
        unsigned int u = (unsigned int)__half_as_ushort(h0) |
                         ((unsigned int)__half_as_ushort(h1) << 16);
        h2out[(size_t)c * NR + row0 + r] = u;
    }
}

// =====================================================================
// Screening GEMM: sim16 = fp16(q @ k^T), masked -> -65504 sentinel.
// Also emits per-(row, ktile) max of the stored fp16 values (g_tmax).
// =====================================================================
__global__ void __launch_bounds__(256, 2) screen_kernel(const unsigned int* __restrict__ mask)
{
    extern __shared__ unsigned int su[];
    unsigned int* qs2 = su;            // [64 d2][128 q]
    unsigned int* ks2 = su + 64 * 128; // [64 d2][128 k]

    const int tid = threadIdx.x;
    const int tx = tid & 15;
    const int ty = tid >> 4;
    const int kc0 = blockIdx.x * 128;
    const int qr0 = blockIdx.y * 128;

#pragma unroll
    for (int it = 0; it < 8; it++) {
        int idx = tid + it * 256;
        int d2 = idx >> 5, c4 = idx & 31;
        *(uint4*)&qs2[d2 * 128 + c4 * 4] =
            *(const uint4*)&g_q16[(size_t)d2 * BB + qr0 + c4 * 4];
        *(uint4*)&ks2[d2 * 128 + c4 * 4] =
            *(const uint4*)&g_k16[(size_t)d2 * NN + kc0 + c4 * 4];
    }
    __syncthreads();

    __half2 acc[8][8];
    const __half2 z2 = __float2half2_rn(0.f);
#pragma unroll
    for (int j = 0; j < 8; j++)
#pragma unroll
        for (int m = 0; m < 8; m++) acc[j][m] = z2;

#pragma unroll 4
    for (int d2 = 0; d2 < 64; d2++) {
        unsigned int a[8], b[8];
        *(uint4*)&a[0] = *(uint4*)&qs2[d2 * 128 + ty * 8];
        *(uint4*)&a[4] = *(uint4*)&qs2[d2 * 128 + ty * 8 + 4];
        *(uint4*)&b[0] = *(uint4*)&ks2[d2 * 128 + tx * 8];
        *(uint4*)&b[4] = *(uint4*)&ks2[d2 * 128 + tx * 8 + 4];
#pragma unroll
        for (int j = 0; j < 8; j++) {
            __half2 av = *reinterpret_cast<__half2*>(&a[j]);
#pragma unroll
            for (int m = 0; m < 8; m++) {
                __half2 bv = *reinterpret_cast<__half2*>(&b[m]);
                acc[j][m] = __hfma2(av, bv, acc[j][m]);
            }
        }
    }

    const __half SENT = __ushort_as_half((unsigned short)0xFBFF);  // -65504
#pragma unroll
    for (int j = 0; j < 8; j++) {
        int row = qr0 + ty * 8 + j;
        const unsigned int* mrow = mask + (size_t)row * NN + kc0 + tx * 8;
        uint4 mA = *(const uint4*)mrow;
        uint4 mB = *(const uint4*)(mrow + 4);
        unsigned int mv[8] = {mA.x, mA.y, mA.z, mA.w, mB.x, mB.y, mB.z, mB.w};
        __half h[8];
        float rowmax = -70000.f;
#pragma unroll
        for (int m = 0; m < 8; m++) {
            float f = __low2float(acc[j][m]) + __high2float(acc[j][m]);
            h[m] = mv[m] ? __float2half_rn(f) : SENT;
            rowmax = fmaxf(rowmax, __half2float(h[m]));   // max over STORED values
        }
        unsigned int pk[4];
#pragma unroll
        for (int p = 0; p < 4; p++)
            pk[p] = (unsigned int)__half_as_ushort(h[2 * p]) |
                    ((unsigned int)__half_as_ushort(h[2 * p + 1]) << 16);
        *(uint4*)&g_sim16[(size_t)row * NN + kc0 + tx * 8] =
            make_uint4(pk[0], pk[1], pk[2], pk[3]);

        // reduce rowmax over the 16 tx lanes (lane bits 0-3)
#pragma unroll
        for (int s = 8; s > 0; s >>= 1)
            rowmax = fmaxf(rowmax, __shfl_xor_sync(0xffffffffu, rowmax, s));
        if (tx == 0)
            g_tmax[(size_t)row * NTILE + blockIdx.x] = rowmax;
    }
}

// =====================================================================
// Select: tile-max pruning with L = MM-th largest tile max (provably
// captures the fp16 top-MM), exact top-MM extraction, fp32 sequential
// rescore (validated numerics), top-16 emit.
// =====================================================================
__device__ __forceinline__ void topk_push(float v, int n, float* lv, int* li)
{
    if (v > lv[15] || (v == lv[15] && n < li[15])) {
        float cv = v; int ci = n;
#pragma unroll
        for (int j = 0; j < 16; j++) {
            bool better = (cv > lv[j]) || (cv == lv[j] && ci < li[j]);
            float tv = lv[j]; int ti = li[j];
            if (better) { lv[j] = cv; li[j] = ci; cv = tv; ci = ti; }
        }
    }
}

__global__ void __launch_bounds__(256) select_rescore_kernel(float* __restrict__ out)
{
    __shared__ float tmax[NTILE];
    __shared__ float tsel[NTILE];
    __shared__ float sv[4096];
    __shared__ int   si[4096];
    __shared__ float rv[256];
    __shared__ int   ri[256];
    __shared__ int   rp[256];
    __shared__ int   anyv[256];
    __shared__ float cval[MM];
    __shared__ int   cidx[MM];
    __shared__ float rsc[MM];
    __shared__ float qsh[128];
    __shared__ float Lsh;

    const int b = blockIdx.x, tid = threadIdx.x;

    if (tid < 128) qsh[tid] = g_qrow[(size_t)b * RDIM + tid];

    // load tile maxes
    {
        float v0 = g_tmax[(size_t)b * NTILE + tid];
        float v1 = g_tmax[(size_t)b * NTILE + tid + 256];
        tmax[tid] = v0; tmax[tid + 256] = v1;
        tsel[tid] = v0; tsel[tid + 256] = v1;
        anyv[tid] = (v0 > -60000.f) | (v1 > -60000.f);
    }
    __syncthreads();
    for (int s = 128; s > 0; s >>= 1) {
        if (tid < s) anyv[tid] |= anyv[tid + s];
        __syncthreads();
    }
    if (tid == 0) g_hasvalid[b] = anyv[0];

    // L = MM-th largest tile max  (guarantees fp16 top-MM capture)
    for (int r = 0; r < MM; r++) {
        float a = tsel[tid], c = tsel[tid + 256];
        rv[tid] = fmaxf(a, c);
        rp[tid] = (a >= c) ? tid : tid + 256;
        __syncthreads();
        for (int s = 128; s > 0; s >>= 1) {
            if (tid < s) {
                if (rv[tid + s] > rv[tid]) { rv[tid] = rv[tid + s]; rp[tid] = rp[tid + s]; }
            }
            __syncthreads();
        }
        if (tid == 0) {
            if (r == MM - 1) Lsh = rv[0];
            tsel[rp[0]] = -INFINITY;
        }
        __syncthreads();
    }
    const float L = Lsh;

    // scan only qualifying tiles; per-thread top-16 lists
    float lv[16]; int li[16];
#pragma unroll
    for (int j = 0; j < 16; j++) { lv[j] = -INFINITY; li[j] = 0x7fffffff; }

    for (int t = 0; t < NTILE; t++) {
        if (tmax[t] < L) continue;           // uniform per block
        if (tid < 128) {
            __half hval = g_sim16[(size_t)b * NN + t * 128 + tid];
            topk_push(__half2float(hval), t * 128 + tid, lv, li);
        }
    }
#pragma unroll
    for (int j = 0; j < 16; j++) { sv[tid * 16 + j] = lv[j]; si[tid * 16 + j] = li[j]; }
    __syncthreads();

    // extract top-MM candidates (value desc, idx asc tie-break)
    int p = 0;
    for (int r = 0; r < MM; r++) {
        float v = (p < 16) ? sv[tid * 16 + p] : -INFINITY;
        int   i = (p < 16) ? si[tid * 16 + p] : 0x7fffffff;
        rv[tid] = v; ri[tid] = i; rp[tid] = tid;
        __syncthreads();
        for (int s = 128; s > 0; s >>= 1) {
            if (tid < s) {
                float v2 = rv[tid + s]; int i2 = ri[tid + s];
                if (v2 > rv[tid] || (v2 == rv[tid] && i2 < ri[tid])) {
                    rv[tid] = v2; ri[tid] = i2; rp[tid] = rp[tid + s];
                }
            }
            __syncthreads();
        }
        if (tid == 0) { cval[r] = rv[0]; cidx[r] = ri[0]; }
        int owner = rp[0];
        __syncthreads();
        if (tid == owner) p++;
        __syncthreads();
    }

    // rescore: one thread per candidate, fp32 sequential accumulation
    // (same expression tree as the passing full-sim kernels)
    if (tid < MM) {
        int idx = cidx[tid];
        if (idx == 0x7fffffff) idx = 0;      // empty-slot guard
        const float4* kr = (const float4*)(g_krow + (size_t)idx * RDIM);
        float acc = 0.f;
        for (int d4 = 0; d4 < 32; d4++) {
            float4 kv = kr[d4];
            float4 qv = *(const float4*)&qsh[d4 * 4];
            acc += qv.x * kv.x + qv.y * kv.y + qv.z * kv.z + qv.w * kv.w;
        }
        rsc[tid] = (cval[tid] < -60000.f) ? -1e9f : acc;
    }
    __syncthreads();

    if (tid == 0) {
        bool used[MM];
#pragma unroll
        for (int c = 0; c < MM; c++) used[c] = false;
        for (int r = 0; r < 16; r++) {
            float bvv = -INFINITY; int bii = 0x7fffffff, bc = -1;
            for (int c = 0; c < MM; c++) {
                if (used[c]) continue;
                if (rsc[c] > bvv || (rsc[c] == bvv && cidx[c] < bii)) {
                    bvv = rsc[c]; bii = cidx[c]; bc = c;
                }
            }
            used[bc] = true;
            out[OUT_TS + b * 16 + r] = bvv;
            out[OUT_TI + b * 16 + r] = (float)bii;
            g_topidx[b * 16 + r] = bii;
        }
    }
}

// =====================================================================
// per-row attention stack
// =====================================================================
__global__ void __launch_bounds__(128) attn_kernel(
    const float* __restrict__ bank_y,
    const float* __restrict__ Ws1, const float* __restrict__ bs1,
    const float* __restrict__ Ws2, const float* __restrict__ bs2,
    const float* __restrict__ Wc1, const float* __restrict__ bc1,
    const float* __restrict__ Wc2, const float* __restrict__ bc2,
    float* __restrict__ out)
{
    __shared__ float y[16][64];
    __shared__ float hbuf[16][128];
    __shared__ float proj[16][128];
    __shared__ float qv[128];
    __shared__ float cmat[128 * 16];
    __shared__ float tred[8 * 16];
    __shared__ float lg[16];
    __shared__ float alpha[16];
    __shared__ int   tix[16];

    const int b = blockIdx.x, tid = threadIdx.x;
    if (tid < 16) tix[tid] = g_topidx[b * 16 + tid];
    qv[tid] = g_qrow[(size_t)b * RDIM + tid];
    __syncthreads();

    for (int e = tid; e < 16 * 64; e += 128)
        y[e >> 6][e & 63] = bank_y[(size_t)tix[e >> 6] * 64 + (e & 63)];
    __syncthreads();

    const int r = tid;
    {
        float4 w[16];
        const float4* W4 = (const float4*)(Ws1 + (size_t)r * 64);
#pragma unroll
        for (int i = 0; i < 16; i++) w[i] = W4[i];
        float bv = bs1[r];
        for (int j = 0; j < 16; j++) {
            float s = bv;
#pragma unroll
            for (int i = 0; i < 16; i++) {
                float4 yy = *(const float4*)&y[j][i * 4];
                s += w[i].x * yy.x + w[i].y * yy.y + w[i].z * yy.z + w[i].w * yy.w;
            }
            hbuf[j][r] = fmaxf(s, 0.f);
        }
    }
    __syncthreads();
    {
        float accp[16];
        float bv = bs2[r];
#pragma unroll
        for (int j = 0; j < 16; j++) accp[j] = bv;
        const float4* W4 = (const float4*)(Ws2 + (size_t)r * 128);
        for (int i = 0; i < 32; i++) {
            float4 w = W4[i];
#pragma unroll
            for (int j = 0; j < 16; j++) {
                float4 hh = *(const float4*)&hbuf[j][i * 4];
                accp[j] += w.x * hh.x + w.y * hh.y + w.z * hh.z + w.w * hh.w;
            }
        }
#pragma unroll
        for (int j = 0; j < 16; j++) proj[j][r] = accp[j];
    }
    __syncthreads();

    {
        float uqr = bc1[r];
        const float4* Wq4 = (const float4*)(Wc1 + (size_t)r * 256);
        for (int i = 0; i < 32; i++) {
            float4 w = Wq4[i];
            float4 qq = *(const float4*)&qv[i * 4];
            uqr += w.x * qq.x + w.y * qq.y + w.z * qq.z + w.w * qq.w;
        }
        float sacc[16];
#pragma unroll
        for (int j = 0; j < 16; j++) sacc[j] = uqr;
        const float4* Wp4 = (const float4*)(Wc1 + (size_t)r * 256 + 128);
        for (int i = 0; i < 32; i++) {
            float4 w = Wp4[i];
#pragma unroll
            for (int j = 0; j < 16; j++) {
                float4 pp = *(const float4*)&proj[j][i * 4];
                sacc[j] += w.x * pp.x + w.y * pp.y + w.z * pp.z + w.w * pp.w;
            }
        }
        float w2r = Wc2[r];
#pragma unroll
        for (int j = 0; j < 16; j++) cmat[r * 16 + j] = tanhf(sacc[j]) * w2r;
    }
    __syncthreads();
    {
        int j = tid & 15, c = tid >> 4;
        float s = 0.f;
        for (int i = 0; i < 16; i++) s += cmat[(c * 16 + i) * 16 + j];
        tred[c * 16 + j] = s;
    }
    __syncthreads();
    if (tid < 16) {
        float s = bc2[0];
        for (int c = 0; c < 8; c++) s += tred[c * 16 + tid];
        lg[tid] = s;
    }
    __syncthreads();
    if (tid == 0) {
        if (g_hasvalid[b]) {
            float mx = lg[0];
            for (int j = 1; j < 16; j++) mx = fmaxf(mx, lg[j]);
            float se = 0.f, ev[16];
            for (int j = 0; j < 16; j++) { ev[j] = expf(lg[j] - mx); se += ev[j]; }
            float isv = 1.0f / se;
            for (int j = 0; j < 16; j++) alpha[j] = ev[j] * isv;
        } else {
            for (int j = 0; j < 16; j++) alpha[j] = 0.f;
        }
    }
    __syncthreads();
    if (tid < 16) out[OUT_AL + b * 16 + tid] = alpha[tid];
    {
        float s = 0.f;
#pragma unroll
        for (int j = 0; j < 16; j++) s += alpha[j] * proj[j][tid];
        g_r[(size_t)b * 128 + tid] = s;
    }
}

// =====================================================================
// z_tilde = has_valid ? relu([z,r] @ Wa^T + ba) : z
// =====================================================================
__global__ void __launch_bounds__(256) aug_kernel(
    const float* __restrict__ zin, const float* __restrict__ Wa,
    const float* __restrict__ ba, float* __restrict__ out)
{
    __shared__ float zr[16 * 640];
    __shared__ int   hv[16];
    const int tid = threadIdx.x, b0 = blockIdx.x * 16;

    for (int e = tid; e < 16 * PDIM; e += 256) {
        int j = e / PDIM, d = e - j * PDIM;
        zr[j * 640 + d] = zin[(size_t)(b0 + j) * PDIM + d];
    }
    for (int e = tid; e < 16 * RDIM; e += 256) {
        int j = e >> 7, d = e & 127;
        zr[j * 640 + PDIM + d] = g_r[(size_t)(b0 + j) * RDIM + d];
    }
    if (tid < 16) hv[tid] = g_hasvalid[b0 + tid];
    __syncthreads();

    for (int half = 0; half < 2; half++) {
        int o = tid + half * 256;
        float acc[16];
        float bv = ba[o];
#pragma unroll
        for (int j = 0; j < 16; j++) acc[j] = bv;
        const float4* W4 = (const float4*)(Wa + (size_t)o * 640);
        for (int i = 0; i < 160; i++) {
            float4 w = W4[i];
#pragma unroll
            for (int j = 0; j < 16; j++) {
                float4 zz = *(const float4*)&zr[j * 640 + i * 4];
                acc[j] += w.x * zz.x + w.y * zz.y + w.z * zz.z + w.w * zz.w;
            }
        }
#pragma unroll
        for (int j = 0; j < 16; j++) {
            float v = hv[j] ? fmaxf(acc[j], 0.f) : zr[j * 640 + o];
            out[(size_t)(b0 + j) * PDIM + o] = v;
        }
    }
}

// =====================================================================
extern "C" void kernel_launch(void* const* d_in, const int* in_sizes, int n_in,
                              void* d_out, int out_size)
{
    const float* z_i    = (const float*)d_in[0];
    const float* g_i    = (const float*)d_in[1];
    const float* bank_z = (const float*)d_in[2];
    const float* bank_g = (const float*)d_in[3];
    const float* bank_y = (const float*)d_in[4];
    const unsigned int* vmask = (const unsigned int*)d_in[5];
    const float* Wq  = (const float*)d_in[6];
    const float* bq  = (const float*)d_in[7];
    const float* Wk  = (const float*)d_in[8];
    const float* bk  = (const float*)d_in[9];
    const float* Ws1 = (const float*)d_in[10];
    const float* bs1 = (const float*)d_in[11];
    const float* Ws2 = (const float*)d_in[12];
    const float* bs2 = (const float*)d_in[13];
    const float* Wc1 = (const float*)d_in[14];
    const float* bc1 = (const float*)d_in[15];
    const float* Wc2 = (const float*)d_in[16];
    const float* bc2 = (const float*)d_in[17];
    const float* Wa  = (const float*)d_in[18];
    const float* ba  = (const float*)d_in[19];
    float* out = (float*)d_out;

    float* p_bcatT; cudaGetSymbolAddress((void**)&p_bcatT, g_bcatT);
    float* p_qcatT; cudaGetSymbolAddress((void**)&p_qcatT, g_qcatT);
    float* p_WqT;   cudaGetSymbolAddress((void**)&p_WqT, g_WqT);
    float* p_WkT;   cudaGetSymbolAddress((void**)&p_WkT, g_WkT);
    float* p_qrow;  cudaGetSymbolAddress((void**)&p_qrow, g_qrow);
    float* p_krow;  cudaGetSymbolAddress((void**)&p_krow, g_krow);
    unsigned int* p_q16; cudaGetSymbolAddress((void**)&p_q16, g_q16);
    unsigned int* p_k16; cudaGetSymbolAddress((void**)&p_k16, g_k16);

    const int smemProj   = 16512 * 4;  // 66 KB
    const int smemScreen = 65536;      // 64 KB

    cudaFuncSetAttribute(proj_gemm_kernel, cudaFuncAttributeMaxDynamicSharedMemorySize, smemProj);
    cudaFuncSetAttribute(screen_kernel, cudaFuncAttributeMaxDynamicSharedMemorySize, smemScreen);

    wT_kernel<<<dim3(24, 4, 2), dim3(32, 8)>>>(Wq, Wk);
    catT_kernel<<<dim3(NN / 32, 24), dim3(32, 8)>>>(bank_z, bank_g, p_bcatT, NN);
    catT_kernel<<<dim3(BB / 32, 24), dim3(32, 8)>>>(z_i, g_i, p_qcatT, BB);

    proj_gemm_kernel<<<BB / 128, 256, smemProj>>>(p_qcatT, p_WqT, bq, p_qrow, p_q16, BB);
    proj_gemm_kernel<<<NN / 128, 256, smemProj>>>(p_bcatT, p_WkT, bk, p_krow, p_k16, NN);

    screen_kernel<<<dim3(NN / 128, BB / 128), 256, smemScreen>>>(vmask);
    select_rescore_kernel<<<BB, 256>>>(out);
    attn_kernel<<<BB, 128>>>(bank_y, Ws1, bs1, Ws2, bs2, Wc1, bc1, Wc2, bc2, out);
    aug_kernel<<<BB / 16, 256>>>(z_i, Wa, ba, out);
}